// round 6
// baseline (speedup 1.0000x reference)
#include <cuda_runtime.h>
#include <math.h>

#define NB_ 16
#define NA_ 5
#define NH_ 96
#define NW_ 96
#define MAXT_ 50
#define NCLS_ 40
#define TROW_ 53
#define CH_ 45
#define NTOT_ (NB_*NA_*NH_*NW_)      // 737280
#define DENSE_BLOCKS 960
#define DENSE_THREADS 256
#define EPT 3                         // 960*256*3 = 737280 exactly
#define TOTAL_BLOCKS (DENSE_BLOCKS + NB_)

__constant__ float c_aw[NA_] = {1.f, 2.f, 4.f, 2.f, 4.f};
__constant__ float c_ah[NA_] = {1.f, 2.f, 4.f, 4.f, 2.f};

struct Acc {
    double S;          // sum softplus(pred_conf) over ALL cells
    double corr_conf;  // corrections at modified cells for cmf*bce
    double mask_bce;   // sum over mask cells of bce(p, tconf=1)
    double lx, ly, lw, lh, lcls;
    int nM;
    int cmf_removed;   // modified cells with cmf==0
    int nGT;
    int nCorrect;
    int nProp;
};
__device__ Acc g_acc;                 // zero-initialized at module load
__device__ unsigned int g_done;       // zero-initialized

__device__ __forceinline__ float softplus_f(float p) {
    return fmaxf(p, 0.f) + log1pf(expf(-fabsf(p)));
}

__global__ void __launch_bounds__(DENSE_THREADS, 6)
yolo_fused_kernel(const float* __restrict__ pred,
                  const float* __restrict__ target,
                  const int* __restrict__ tsz,
                  float* __restrict__ out) {
    const int bid = blockIdx.x;
    const int tid = threadIdx.x;

    if (bid < DENSE_BLOCKS) {
        // ===================== DENSE path: conf-channel reduction =====================
        const int gt = bid * DENSE_THREADS + tid;
        float sp = 0.f;
        int np = 0;
        #pragma unroll
        for (int k = 0; k < EPT; k++) {
            int i = gt + k * (DENSE_BLOCKS * DENSE_THREADS);
            float p = __ldg(pred + (size_t)i * CH_);
            sp += softplus_f(p);
            np += (p > 0.f) ? 1 : 0;
        }
        #pragma unroll
        for (int off = 16; off > 0; off >>= 1) {
            sp += __shfl_down_sync(0xffffffffu, sp, off);
            np += __shfl_down_sync(0xffffffffu, np, off);
        }
        __shared__ float ssp[8];
        __shared__ int snp[8];
        int wid = tid >> 5, lid = tid & 31;
        if (lid == 0) { ssp[wid] = sp; snp[wid] = np; }
        __syncthreads();
        if (wid == 0) {
            sp = (lid < 8) ? ssp[lid] : 0.f;
            np = (lid < 8) ? snp[lid] : 0;
            #pragma unroll
            for (int off = 4; off > 0; off >>= 1) {
                sp += __shfl_down_sync(0xffffffffu, sp, off);
                np += __shfl_down_sync(0xffffffffu, np, off);
            }
            if (lid == 0) {
                atomicAdd(&g_acc.S, (double)sp);
                atomicAdd(&g_acc.nProp, np);
            }
        }
    } else {
        // ===================== BUILD path (one block per batch) =====================
        const int b = bid - DENSE_BLOCKS;
        __shared__ float s_gx[MAXT_], s_gy[MAXT_], s_gw[MAXT_], s_gh[MAXT_];
        __shared__ float s_tx[MAXT_], s_ty[MAXT_], s_tw[MAXT_], s_th[MAXT_];
        __shared__ int   s_cell[MAXT_];            // cj*NW + ci
        __shared__ int   s_best[MAXT_], s_lbl[MAXT_], s_ign[MAXT_];  // ign = 5-bit mask
        __shared__ int   s_rlist[MAXT_];
        __shared__ int   s_ne;

        const int size = tsz[b];
        if (tid == 0) s_ne = 0;

        // ---- Phase A: per-target independent quantities (parallel) ----
        if (tid < size) {
            const float* row = target + ((size_t)b * MAXT_ + tid) * TROW_;
            const float inv = 1.f / 16.f;
            float gx = row[0] * inv;
            float gy = row[1] * inv;
            float gh = row[3] * inv;   // row[3] = h
            float gw = row[4] * inv;   // row[4] = w
            int gi = (int)gx;
            int gj = (int)gy;
            float bestv = -1e30f; int bestn = 0;
            int ignm = 0;
            float ga = (gw + 1.f) * (gh + 1.f);
            #pragma unroll
            for (int a = 0; a < NA_; a++) {
                float iw = fmaxf(fminf(gw, c_aw[a]) + 1.f, 0.f);
                float ih = fmaxf(fminf(gh, c_ah[a]) + 1.f, 0.f);
                float inter = iw * ih;
                float aa = (c_aw[a] + 1.f) * (c_ah[a] + 1.f);
                float iou = inter / (ga + aa - inter + 1e-16f);
                if (iou > 0.5f) ignm |= (1 << a);
                if (iou > bestv) { bestv = iou; bestn = a; }
            }
            const float* cl = row + 13;
            float bv = cl[0]; int ba = 0;
            #pragma unroll
            for (int k = 1; k < NCLS_; k++) {
                float v = cl[k];
                if (v > bv) { bv = v; ba = k; }
            }
            s_gx[tid] = gx; s_gy[tid] = gy; s_gw[tid] = gw; s_gh[tid] = gh;
            s_tx[tid] = gx - (float)gi;
            s_ty[tid] = gy - (float)gj;
            s_tw[tid] = logf(gw / c_aw[bestn] + 1e-16f);
            s_th[tid] = logf(gh / c_ah[bestn] + 1e-16f);
            s_cell[tid] = gj * NW_ + gi;
            s_best[tid] = bestn; s_lbl[tid] = ba; s_ign[tid] = ignm;
        }
        __syncthreads();

        // ---- Phase B: cell-representative detection + nCorrect (parallel) ----
        if (tid < size) {
            int cell = s_cell[tid];
            bool rep = true;
            for (int t = 0; t < tid; t++)
                if (s_cell[t] == cell) { rep = false; break; }
            if (rep) {
                int pos = atomicAdd(&s_ne, 1);
                s_rlist[pos] = tid;
            }

            // nCorrect: scan-order independent (per target)
            int bn = s_best[tid];
            int ci = cell % NW_, cj = cell / NW_;
            const float* c = pred + ((((size_t)b * NA_ + bn) * NH_ + cj) * NW_ + ci) * CH_;
            float pc = c[0], x = c[1], y = c[2], h = c[3], w = c[4];
            float bv = c[5]; int ba = 0;
            #pragma unroll
            for (int k = 1; k < NCLS_; k++) {
                float v = c[5 + k];
                if (v > bv) { bv = v; ba = k; }
            }
            float px = x + (float)ci;
            float py = y + (float)cj;
            float pw = expf(w) * c_aw[bn];
            float ph = expf(h) * c_ah[bn];
            float gx = s_gx[tid], gy = s_gy[tid], gw = s_gw[tid], gh = s_gh[tid];
            float gx1 = gx - gw * 0.5f, gx2 = gx + gw * 0.5f;
            float gy1 = gy - gh * 0.5f, gy2 = gy + gh * 0.5f;
            float px1 = px - pw * 0.5f, px2 = px + pw * 0.5f;
            float py1 = py - ph * 0.5f, py2 = py + ph * 0.5f;
            float iw = fmaxf(fminf(gx2, px2) - fmaxf(gx1, px1) + 1.f, 0.f);
            float ih = fmaxf(fminf(gy2, py2) - fmaxf(gy1, py1) + 1.f, 0.f);
            float inter = iw * ih;
            float gaA = (gx2 - gx1 + 1.f) * (gy2 - gy1 + 1.f);
            float paA = (px2 - px1 + 1.f) * (py2 - py1 + 1.f);
            float iou = inter / (gaA + paA - inter + 1e-16f);
            if (iou > 0.5f && ba == s_lbl[tid] && pc > 0.5f)
                atomicAdd(&g_acc.nCorrect, 1);
        }
        if (tid == 0 && size > 0) atomicAdd(&g_acc.nGT, size);
        __syncthreads();

        // ---- Phase C: per-(cell,anchor) replay restricted to that cell (parallel) ----
        const int ne = s_ne;
        for (int idx = tid; idx < ne * NA_; idx += blockDim.x) {
            int e = idx / NA_, a = idx % NA_;
            int cell = s_cell[s_rlist[e]];
            int cm = 1, m = 0, src = -1;
            for (int t = 0; t < size; t++) {
                if (s_cell[t] == cell) {
                    if ((s_ign[t] >> a) & 1) cm = 0;
                    if (s_best[t] == a) { cm = 1; m = 1; src = t; }
                }
            }
            int ci = cell % NW_, cj = cell / NW_;
            const float* c = pred + ((((size_t)b * NA_ + a) * NH_ + cj) * NW_ + ci) * CH_;
            float p = c[0];
            int cmf = (cm != m);
            if (cmf) {
                if (m) atomicAdd(&g_acc.corr_conf, (double)(-p));
                // cm=1,m=0: bce == softplus(p) already counted by dense S; correction 0
            } else {
                atomicAdd(&g_acc.corr_conf, (double)(-softplus_f(p)));
                atomicAdd(&g_acc.cmf_removed, 1);
            }
            if (m) {
                atomicAdd(&g_acc.nM, 1);
                float bce1 = fmaxf(p, 0.f) - p + log1pf(expf(-fabsf(p)));
                atomicAdd(&g_acc.mask_bce, (double)bce1);
                float x = c[1], y = c[2], h = c[3], w = c[4];
                float dx = x - s_tx[src];
                float dy = y - s_ty[src];
                float dw = w - s_tw[src];
                float dh = h - s_th[src];
                atomicAdd(&g_acc.lx, (double)(dx * dx));
                atomicAdd(&g_acc.ly, (double)(dy * dy));
                atomicAdd(&g_acc.lw, (double)(dw * dw));
                atomicAdd(&g_acc.lh, (double)(dh * dh));
                float mx = c[5];
                #pragma unroll
                for (int k = 1; k < NCLS_; k++) mx = fmaxf(mx, c[5 + k]);
                float s = 0.f;
                #pragma unroll
                for (int k = 0; k < NCLS_; k++) s += expf(c[5 + k] - mx);
                float ce = mx + logf(s) - c[5 + s_lbl[src]];
                atomicAdd(&g_acc.lcls, (double)ce);
            }
        }
    }

    // ===================== Last block finalizes + resets state =====================
    __syncthreads();
    if (tid == 0) {
        __threadfence();
        unsigned int old = atomicAdd(&g_done, 1u);
        if (old == gridDim.x - 1) {
            __threadfence();
            Acc a = g_acc;
            double sum_cmf = (double)NTOT_ - (double)a.cmf_removed;
            double nM = (double)a.nM;
            double conf = (a.S + a.corr_conf) / sum_cmf + a.mask_bce / nM;
            double coord = (a.lx + a.ly + a.lw + a.lh) / nM;
            double cls = a.lcls / (nM * (double)NB_);
            out[0] = (float)(coord + conf + cls);
            out[1] = (float)coord;
            out[2] = (float)conf;
            out[3] = (float)cls;
            float nGT = fmaxf((float)a.nGT, 1.f);
            out[4] = (float)a.nCorrect / nGT;
            out[5] = (a.nProp > 0) ? ((float)a.nCorrect / fmaxf((float)a.nProp, 1.f)) : 1.f;
            // Reset accumulators for the next graph replay (deterministic:
            // module-load zero-init covers the very first call).
            g_acc.S = 0.0; g_acc.corr_conf = 0.0; g_acc.mask_bce = 0.0;
            g_acc.lx = 0.0; g_acc.ly = 0.0; g_acc.lw = 0.0; g_acc.lh = 0.0;
            g_acc.lcls = 0.0;
            g_acc.nM = 0; g_acc.cmf_removed = 0; g_acc.nGT = 0;
            g_acc.nCorrect = 0; g_acc.nProp = 0;
            __threadfence();
            g_done = 0u;
        }
    }
}

extern "C" void kernel_launch(void* const* d_in, const int* in_sizes, int n_in,
                              void* d_out, int out_size) {
    const float* pred = (const float*)d_in[0];
    const float* target = (const float*)d_in[1];
    const int* tsz = (const int*)d_in[2];
    float* out = (float*)d_out;
    yolo_fused_kernel<<<TOTAL_BLOCKS, DENSE_THREADS>>>(pred, target, tsz, out);
}

// round 9
// speedup vs baseline: 1.1364x; 1.1364x over previous
#include <cuda_runtime.h>
#include <math.h>

#define NB_ 16
#define NA_ 5
#define NH_ 96
#define NW_ 96
#define MAXT_ 50
#define NCLS_ 40
#define TROW_ 53
#define CH_ 45
#define NTOT_ (NB_*NA_*NH_*NW_)      // 737280
#define DENSE_BLOCKS 720
#define DENSE_THREADS 256
#define EPT 4                         // 720*256*4 = 737280 exactly
#define TOTAL_BLOCKS (NB_ + DENSE_BLOCKS)   // 736 < 888 resident cap -> ONE wave

__constant__ float c_aw[NA_] = {1.f, 2.f, 4.f, 2.f, 4.f};
__constant__ float c_ah[NA_] = {1.f, 2.f, 4.f, 4.f, 2.f};

struct Acc {
    double S;          // sum softplus(pred_conf) over ALL cells
    double corr_conf;  // corrections at modified cells for cmf*bce
    double mask_bce;   // sum over mask cells of bce(p, tconf=1)
    double lx, ly, lw, lh, lcls;
    int nM;
    int cmf_removed;   // modified cells with cmf==0
    int nGT;
    int nCorrect;
    int nProp;
};
__device__ Acc g_acc;                 // zero-initialized at module load
__device__ unsigned int g_done;       // zero-initialized

__device__ __forceinline__ float softplus_f(float p) {
    return fmaxf(p, 0.f) + log1pf(expf(-fabsf(p)));
}

__global__ void __launch_bounds__(DENSE_THREADS, 6)
yolo_fused_kernel(const float* __restrict__ pred,
                  const float* __restrict__ target,
                  const int* __restrict__ tsz,
                  float* __restrict__ out) {
    const int bid = blockIdx.x;
    const int tid = threadIdx.x;

    if (bid >= NB_) {
        // ===================== DENSE path: conf-channel reduction =====================
        const int gt = (bid - NB_) * DENSE_THREADS + tid;
        float sp = 0.f;
        int np = 0;
        #pragma unroll
        for (int k = 0; k < EPT; k++) {
            int i = gt + k * (DENSE_BLOCKS * DENSE_THREADS);
            float p = __ldg(pred + (size_t)i * CH_);
            sp += softplus_f(p);
            np += (p > 0.f) ? 1 : 0;
        }
        #pragma unroll
        for (int off = 16; off > 0; off >>= 1) {
            sp += __shfl_down_sync(0xffffffffu, sp, off);
            np += __shfl_down_sync(0xffffffffu, np, off);
        }
        __shared__ float ssp[8];
        __shared__ int snp[8];
        int wid = tid >> 5, lid = tid & 31;
        if (lid == 0) { ssp[wid] = sp; snp[wid] = np; }
        __syncthreads();
        if (wid == 0) {
            sp = (lid < 8) ? ssp[lid] : 0.f;
            np = (lid < 8) ? snp[lid] : 0;
            #pragma unroll
            for (int off = 4; off > 0; off >>= 1) {
                sp += __shfl_down_sync(0xffffffffu, sp, off);
                np += __shfl_down_sync(0xffffffffu, np, off);
            }
            if (lid == 0) {
                atomicAdd(&g_acc.S, (double)sp);
                atomicAdd(&g_acc.nProp, np);
            }
        }
    } else {
        // ===================== BUILD path (one block per batch, launched FIRST) ========
        const int b = bid;
        __shared__ float s_gx[MAXT_], s_gy[MAXT_], s_gw[MAXT_], s_gh[MAXT_];
        __shared__ float s_tx[MAXT_], s_ty[MAXT_], s_tw[MAXT_], s_th[MAXT_];
        __shared__ int   s_cell[MAXT_];            // cj*NW + ci
        __shared__ int   s_best[MAXT_], s_lbl[MAXT_], s_ign[MAXT_];  // ign = 5-bit mask
        __shared__ int   s_rlist[MAXT_];
        __shared__ int   s_ne;

        const int size = tsz[b];
        if (tid == 0) s_ne = 0;

        // ---- Phase A: per-target independent quantities (parallel) ----
        if (tid < size) {
            const float* row = target + ((size_t)b * MAXT_ + tid) * TROW_;
            const float inv = 1.f / 16.f;
            float gx = row[0] * inv;
            float gy = row[1] * inv;
            float gh = row[3] * inv;   // row[3] = h
            float gw = row[4] * inv;   // row[4] = w
            int gi = (int)gx;
            int gj = (int)gy;
            float bestv = -1e30f; int bestn = 0;
            int ignm = 0;
            float ga = (gw + 1.f) * (gh + 1.f);
            #pragma unroll
            for (int a = 0; a < NA_; a++) {
                float iw = fmaxf(fminf(gw, c_aw[a]) + 1.f, 0.f);
                float ih = fmaxf(fminf(gh, c_ah[a]) + 1.f, 0.f);
                float inter = iw * ih;
                float aa = (c_aw[a] + 1.f) * (c_ah[a] + 1.f);
                float iou = inter / (ga + aa - inter + 1e-16f);
                if (iou > 0.5f) ignm |= (1 << a);
                if (iou > bestv) { bestv = iou; bestn = a; }
            }
            const float* cl = row + 13;
            float bv = cl[0]; int ba = 0;
            #pragma unroll
            for (int k = 1; k < NCLS_; k++) {
                float v = cl[k];
                if (v > bv) { bv = v; ba = k; }
            }
            s_gx[tid] = gx; s_gy[tid] = gy; s_gw[tid] = gw; s_gh[tid] = gh;
            s_tx[tid] = gx - (float)gi;
            s_ty[tid] = gy - (float)gj;
            s_tw[tid] = logf(gw / c_aw[bestn] + 1e-16f);
            s_th[tid] = logf(gh / c_ah[bestn] + 1e-16f);
            s_cell[tid] = gj * NW_ + gi;
            s_best[tid] = bestn; s_lbl[tid] = ba; s_ign[tid] = ignm;
        }
        __syncthreads();

        // ---- Phase B: cell-representative detection + nCorrect (parallel) ----
        if (tid < size) {
            int cell = s_cell[tid];
            bool rep = true;
            for (int t = 0; t < tid; t++)
                if (s_cell[t] == cell) { rep = false; break; }
            if (rep) {
                int pos = atomicAdd(&s_ne, 1);
                s_rlist[pos] = tid;
            }

            // nCorrect: scan-order independent (per target)
            int bn = s_best[tid];
            int ci = cell % NW_, cj = cell / NW_;
            const float* c = pred + ((((size_t)b * NA_ + bn) * NH_ + cj) * NW_ + ci) * CH_;
            float pc = c[0], x = c[1], y = c[2], h = c[3], w = c[4];
            float bv = c[5]; int ba = 0;
            #pragma unroll
            for (int k = 1; k < NCLS_; k++) {
                float v = c[5 + k];
                if (v > bv) { bv = v; ba = k; }
            }
            float px = x + (float)ci;
            float py = y + (float)cj;
            float pw = expf(w) * c_aw[bn];
            float ph = expf(h) * c_ah[bn];
            float gx = s_gx[tid], gy = s_gy[tid], gw = s_gw[tid], gh = s_gh[tid];
            float gx1 = gx - gw * 0.5f, gx2 = gx + gw * 0.5f;
            float gy1 = gy - gh * 0.5f, gy2 = gy + gh * 0.5f;
            float px1 = px - pw * 0.5f, px2 = px + pw * 0.5f;
            float py1 = py - ph * 0.5f, py2 = py + ph * 0.5f;
            float iw = fmaxf(fminf(gx2, px2) - fmaxf(gx1, px1) + 1.f, 0.f);
            float ih = fmaxf(fminf(gy2, py2) - fmaxf(gy1, py1) + 1.f, 0.f);
            float inter = iw * ih;
            float gaA = (gx2 - gx1 + 1.f) * (gy2 - gy1 + 1.f);
            float paA = (px2 - px1 + 1.f) * (py2 - py1 + 1.f);
            float iou = inter / (gaA + paA - inter + 1e-16f);
            if (iou > 0.5f && ba == s_lbl[tid] && pc > 0.5f)
                atomicAdd(&g_acc.nCorrect, 1);
        }
        if (tid == 0 && size > 0) atomicAdd(&g_acc.nGT, size);
        __syncthreads();

        // ---- Phase C: per-(cell,anchor) replay restricted to that cell (parallel) ----
        const int ne = s_ne;
        for (int idx = tid; idx < ne * NA_; idx += blockDim.x) {
            int e = idx / NA_, a = idx % NA_;
            int cell = s_cell[s_rlist[e]];
            int cm = 1, m = 0, src = -1;
            for (int t = 0; t < size; t++) {
                if (s_cell[t] == cell) {
                    if ((s_ign[t] >> a) & 1) cm = 0;
                    if (s_best[t] == a) { cm = 1; m = 1; src = t; }
                }
            }
            int ci = cell % NW_, cj = cell / NW_;
            const float* c = pred + ((((size_t)b * NA_ + a) * NH_ + cj) * NW_ + ci) * CH_;
            float p = c[0];
            int cmf = (cm != m);
            if (cmf) {
                if (m) atomicAdd(&g_acc.corr_conf, (double)(-p));
                // cm=1,m=0: bce == softplus(p) already counted by dense S; correction 0
            } else {
                atomicAdd(&g_acc.corr_conf, (double)(-softplus_f(p)));
                atomicAdd(&g_acc.cmf_removed, 1);
            }
            if (m) {
                atomicAdd(&g_acc.nM, 1);
                float bce1 = fmaxf(p, 0.f) - p + log1pf(expf(-fabsf(p)));
                atomicAdd(&g_acc.mask_bce, (double)bce1);
                float x = c[1], y = c[2], h = c[3], w = c[4];
                float dx = x - s_tx[src];
                float dy = y - s_ty[src];
                float dw = w - s_tw[src];
                float dh = h - s_th[src];
                atomicAdd(&g_acc.lx, (double)(dx * dx));
                atomicAdd(&g_acc.ly, (double)(dy * dy));
                atomicAdd(&g_acc.lw, (double)(dw * dw));
                atomicAdd(&g_acc.lh, (double)(dh * dh));
                float mx = c[5];
                #pragma unroll
                for (int k = 1; k < NCLS_; k++) mx = fmaxf(mx, c[5 + k]);
                float s = 0.f;
                #pragma unroll
                for (int k = 0; k < NCLS_; k++) s += expf(c[5 + k] - mx);
                float ce = mx + logf(s) - c[5 + s_lbl[src]];
                atomicAdd(&g_acc.lcls, (double)ce);
            }
        }
    }

    // ===================== Last block finalizes + resets state =====================
    __syncthreads();
    if (tid == 0) {
        __threadfence();
        unsigned int old = atomicAdd(&g_done, 1u);
        if (old == gridDim.x - 1) {
            __threadfence();
            Acc a = g_acc;
            double sum_cmf = (double)NTOT_ - (double)a.cmf_removed;
            double nM = (double)a.nM;
            double conf = (a.S + a.corr_conf) / sum_cmf + a.mask_bce / nM;
            double coord = (a.lx + a.ly + a.lw + a.lh) / nM;
            double cls = a.lcls / (nM * (double)NB_);
            out[0] = (float)(coord + conf + cls);
            out[1] = (float)coord;
            out[2] = (float)conf;
            out[3] = (float)cls;
            float nGT = fmaxf((float)a.nGT, 1.f);
            out[4] = (float)a.nCorrect / nGT;
            out[5] = (a.nProp > 0) ? ((float)a.nCorrect / fmaxf((float)a.nProp, 1.f)) : 1.f;
            // Reset accumulators for the next graph replay (deterministic:
            // module-load zero-init covers the very first call).
            g_acc.S = 0.0; g_acc.corr_conf = 0.0; g_acc.mask_bce = 0.0;
            g_acc.lx = 0.0; g_acc.ly = 0.0; g_acc.lw = 0.0; g_acc.lh = 0.0;
            g_acc.lcls = 0.0;
            g_acc.nM = 0; g_acc.cmf_removed = 0; g_acc.nGT = 0;
            g_acc.nCorrect = 0; g_acc.nProp = 0;
            __threadfence();
            g_done = 0u;
        }
    }
}

extern "C" void kernel_launch(void* const* d_in, const int* in_sizes, int n_in,
                              void* d_out, int out_size) {
    const float* pred = (const float*)d_in[0];
    const float* target = (const float*)d_in[1];
    const int* tsz = (const int*)d_in[2];
    float* out = (float*)d_out;
    yolo_fused_kernel<<<TOTAL_BLOCKS, DENSE_THREADS>>>(pred, target, tsz, out);
}

// round 11
// speedup vs baseline: 1.3025x; 1.1462x over previous
#include <cuda_runtime.h>
#include <math.h>

#define NB_ 16
#define NA_ 5
#define NH_ 96
#define NW_ 96
#define MAXT_ 50
#define NCLS_ 40
#define TROW_ 53
#define CH_ 45
#define NTOT_ (NB_*NA_*NH_*NW_)      // 737280
#define DENSE_BLOCKS 360
#define DENSE_THREADS 256
#define EPT 8                         // 360*256*8 = 737280 exactly
#define TOTAL_BLOCKS (NB_ + DENSE_BLOCKS)   // 376 blocks, one wave

__constant__ float c_aw[NA_] = {1.f, 2.f, 4.f, 2.f, 4.f};
__constant__ float c_ah[NA_] = {1.f, 2.f, 4.f, 4.f, 2.f};

struct Acc {
    double S;          // sum softplus(pred_conf) over ALL cells
    double corr_conf;  // corrections at modified cells for cmf*bce
    double mask_bce;   // sum over mask cells of bce(p, tconf=1)
    double lx, ly, lw, lh, lcls;
    int nM;
    int cmf_removed;   // modified cells with cmf==0
    int nGT;
    int nCorrect;
    int nProp;
};
__device__ Acc g_acc;                 // zero-initialized at module load
__device__ unsigned int g_done;       // zero-initialized

__device__ __forceinline__ float softplus_f(float p) {
    return fmaxf(p, 0.f) + log1pf(expf(-fabsf(p)));
}

__global__ void __launch_bounds__(DENSE_THREADS)
yolo_fused_kernel(const float* __restrict__ pred,
                  const float* __restrict__ target,
                  const int* __restrict__ tsz,
                  float* __restrict__ out) {
    const int bid = blockIdx.x;
    const int tid = threadIdx.x;

    if (bid >= NB_) {
        // ===================== DENSE path: conf-channel reduction =====================
        const int gt = (bid - NB_) * DENSE_THREADS + tid;
        // Phase 1: issue ALL loads first (independent addresses, 32-bit math,
        // L2-only caching: these lines are single-use).
        float v[EPT];
        #pragma unroll
        for (int k = 0; k < EPT; k++) {
            int i = gt + k * (DENSE_BLOCKS * DENSE_THREADS);
            v[k] = __ldcg(pred + i * CH_);   // i*45 < 2^25, fits int
        }
        // Phase 2: compute
        float sp = 0.f;
        int np = 0;
        #pragma unroll
        for (int k = 0; k < EPT; k++) {
            sp += softplus_f(v[k]);
            np += (v[k] > 0.f) ? 1 : 0;
        }
        #pragma unroll
        for (int off = 16; off > 0; off >>= 1) {
            sp += __shfl_down_sync(0xffffffffu, sp, off);
            np += __shfl_down_sync(0xffffffffu, np, off);
        }
        __shared__ float ssp[8];
        __shared__ int snp[8];
        int wid = tid >> 5, lid = tid & 31;
        if (lid == 0) { ssp[wid] = sp; snp[wid] = np; }
        __syncthreads();
        if (wid == 0) {
            sp = (lid < 8) ? ssp[lid] : 0.f;
            np = (lid < 8) ? snp[lid] : 0;
            #pragma unroll
            for (int off = 4; off > 0; off >>= 1) {
                sp += __shfl_down_sync(0xffffffffu, sp, off);
                np += __shfl_down_sync(0xffffffffu, np, off);
            }
            if (lid == 0) {
                atomicAdd(&g_acc.S, (double)sp);
                atomicAdd(&g_acc.nProp, np);
            }
        }
    } else {
        // ===================== BUILD path (one block per batch, bid 0..15) =====
        const int b = bid;
        __shared__ float s_gx[MAXT_], s_gy[MAXT_], s_gw[MAXT_], s_gh[MAXT_];
        __shared__ float s_tx[MAXT_], s_ty[MAXT_], s_tw[MAXT_], s_th[MAXT_];
        __shared__ int   s_cell[MAXT_];            // cj*NW + ci
        __shared__ int   s_best[MAXT_], s_lbl[MAXT_], s_ign[MAXT_];  // ign = 5-bit mask
        __shared__ int   s_rlist[MAXT_];
        __shared__ int   s_ne;

        const int size = tsz[b];
        if (tid == 0) s_ne = 0;

        // ---- Phase A: per-target independent quantities (parallel) ----
        if (tid < size) {
            const float* row = target + ((size_t)b * MAXT_ + tid) * TROW_;
            const float inv = 1.f / 16.f;
            float gx = row[0] * inv;
            float gy = row[1] * inv;
            float gh = row[3] * inv;   // row[3] = h
            float gw = row[4] * inv;   // row[4] = w
            int gi = (int)gx;
            int gj = (int)gy;
            float bestv = -1e30f; int bestn = 0;
            int ignm = 0;
            float ga = (gw + 1.f) * (gh + 1.f);
            #pragma unroll
            for (int a = 0; a < NA_; a++) {
                float iw = fmaxf(fminf(gw, c_aw[a]) + 1.f, 0.f);
                float ih = fmaxf(fminf(gh, c_ah[a]) + 1.f, 0.f);
                float inter = iw * ih;
                float aa = (c_aw[a] + 1.f) * (c_ah[a] + 1.f);
                float iou = inter / (ga + aa - inter + 1e-16f);
                if (iou > 0.5f) ignm |= (1 << a);
                if (iou > bestv) { bestv = iou; bestn = a; }
            }
            const float* cl = row + 13;
            float bv = cl[0]; int ba = 0;
            #pragma unroll
            for (int k = 1; k < NCLS_; k++) {
                float v = cl[k];
                if (v > bv) { bv = v; ba = k; }
            }
            s_gx[tid] = gx; s_gy[tid] = gy; s_gw[tid] = gw; s_gh[tid] = gh;
            s_tx[tid] = gx - (float)gi;
            s_ty[tid] = gy - (float)gj;
            s_tw[tid] = logf(gw / c_aw[bestn] + 1e-16f);
            s_th[tid] = logf(gh / c_ah[bestn] + 1e-16f);
            s_cell[tid] = gj * NW_ + gi;
            s_best[tid] = bestn; s_lbl[tid] = ba; s_ign[tid] = ignm;
        }
        __syncthreads();

        // ---- Phase B: cell-representative detection + nCorrect (parallel) ----
        if (tid < size) {
            int cell = s_cell[tid];
            bool rep = true;
            for (int t = 0; t < tid; t++)
                if (s_cell[t] == cell) { rep = false; break; }
            if (rep) {
                int pos = atomicAdd(&s_ne, 1);
                s_rlist[pos] = tid;
            }

            // nCorrect: scan-order independent (per target)
            int bn = s_best[tid];
            int ci = cell % NW_, cj = cell / NW_;
            const float* c = pred + ((((size_t)b * NA_ + bn) * NH_ + cj) * NW_ + ci) * CH_;
            float pc = c[0], x = c[1], y = c[2], h = c[3], w = c[4];
            float bv = c[5]; int ba = 0;
            #pragma unroll
            for (int k = 1; k < NCLS_; k++) {
                float v = c[5 + k];
                if (v > bv) { bv = v; ba = k; }
            }
            float px = x + (float)ci;
            float py = y + (float)cj;
            float pw = expf(w) * c_aw[bn];
            float ph = expf(h) * c_ah[bn];
            float gx = s_gx[tid], gy = s_gy[tid], gw = s_gw[tid], gh = s_gh[tid];
            float gx1 = gx - gw * 0.5f, gx2 = gx + gw * 0.5f;
            float gy1 = gy - gh * 0.5f, gy2 = gy + gh * 0.5f;
            float px1 = px - pw * 0.5f, px2 = px + pw * 0.5f;
            float py1 = py - ph * 0.5f, py2 = py + ph * 0.5f;
            float iw = fmaxf(fminf(gx2, px2) - fmaxf(gx1, px1) + 1.f, 0.f);
            float ih = fmaxf(fminf(gy2, py2) - fmaxf(gy1, py1) + 1.f, 0.f);
            float inter = iw * ih;
            float gaA = (gx2 - gx1 + 1.f) * (gy2 - gy1 + 1.f);
            float paA = (px2 - px1 + 1.f) * (py2 - py1 + 1.f);
            float iou = inter / (gaA + paA - inter + 1e-16f);
            if (iou > 0.5f && ba == s_lbl[tid] && pc > 0.5f)
                atomicAdd(&g_acc.nCorrect, 1);
        }
        if (tid == 0 && size > 0) atomicAdd(&g_acc.nGT, size);
        __syncthreads();

        // ---- Phase C: per-(cell,anchor) replay restricted to that cell (parallel) ----
        const int ne = s_ne;
        for (int idx = tid; idx < ne * NA_; idx += blockDim.x) {
            int e = idx / NA_, a = idx % NA_;
            int cell = s_cell[s_rlist[e]];
            int cm = 1, m = 0, src = -1;
            for (int t = 0; t < size; t++) {
                if (s_cell[t] == cell) {
                    if ((s_ign[t] >> a) & 1) cm = 0;
                    if (s_best[t] == a) { cm = 1; m = 1; src = t; }
                }
            }
            int ci = cell % NW_, cj = cell / NW_;
            const float* c = pred + ((((size_t)b * NA_ + a) * NH_ + cj) * NW_ + ci) * CH_;
            float p = c[0];
            int cmf = (cm != m);
            if (cmf) {
                if (m) atomicAdd(&g_acc.corr_conf, (double)(-p));
                // cm=1,m=0: bce == softplus(p) already counted by dense S; correction 0
            } else {
                atomicAdd(&g_acc.corr_conf, (double)(-softplus_f(p)));
                atomicAdd(&g_acc.cmf_removed, 1);
            }
            if (m) {
                atomicAdd(&g_acc.nM, 1);
                float bce1 = fmaxf(p, 0.f) - p + log1pf(expf(-fabsf(p)));
                atomicAdd(&g_acc.mask_bce, (double)bce1);
                float x = c[1], y = c[2], h = c[3], w = c[4];
                float dx = x - s_tx[src];
                float dy = y - s_ty[src];
                float dw = w - s_tw[src];
                float dh = h - s_th[src];
                atomicAdd(&g_acc.lx, (double)(dx * dx));
                atomicAdd(&g_acc.ly, (double)(dy * dy));
                atomicAdd(&g_acc.lw, (double)(dw * dw));
                atomicAdd(&g_acc.lh, (double)(dh * dh));
                float mx = c[5];
                #pragma unroll
                for (int k = 1; k < NCLS_; k++) mx = fmaxf(mx, c[5 + k]);
                float s = 0.f;
                #pragma unroll
                for (int k = 0; k < NCLS_; k++) s += expf(c[5 + k] - mx);
                float ce = mx + logf(s) - c[5 + s_lbl[src]];
                atomicAdd(&g_acc.lcls, (double)ce);
            }
        }
    }

    // ===================== Last block finalizes + resets state =====================
    __syncthreads();
    if (tid == 0) {
        __threadfence();
        unsigned int old = atomicAdd(&g_done, 1u);
        if (old == gridDim.x - 1) {
            __threadfence();
            Acc a = g_acc;
            double sum_cmf = (double)NTOT_ - (double)a.cmf_removed;
            double nM = (double)a.nM;
            double conf = (a.S + a.corr_conf) / sum_cmf + a.mask_bce / nM;
            double coord = (a.lx + a.ly + a.lw + a.lh) / nM;
            double cls = a.lcls / (nM * (double)NB_);
            out[0] = (float)(coord + conf + cls);
            out[1] = (float)coord;
            out[2] = (float)conf;
            out[3] = (float)cls;
            float nGT = fmaxf((float)a.nGT, 1.f);
            out[4] = (float)a.nCorrect / nGT;
            out[5] = (a.nProp > 0) ? ((float)a.nCorrect / fmaxf((float)a.nProp, 1.f)) : 1.f;
            // Reset accumulators for the next graph replay (deterministic:
            // module-load zero-init covers the very first call).
            g_acc.S = 0.0; g_acc.corr_conf = 0.0; g_acc.mask_bce = 0.0;
            g_acc.lx = 0.0; g_acc.ly = 0.0; g_acc.lw = 0.0; g_acc.lh = 0.0;
            g_acc.lcls = 0.0;
            g_acc.nM = 0; g_acc.cmf_removed = 0; g_acc.nGT = 0;
            g_acc.nCorrect = 0; g_acc.nProp = 0;
            __threadfence();
            g_done = 0u;
        }
    }
}

extern "C" void kernel_launch(void* const* d_in, const int* in_sizes, int n_in,
                              void* d_out, int out_size) {
    const float* pred = (const float*)d_in[0];
    const float* target = (const float*)d_in[1];
    const int* tsz = (const int*)d_in[2];
    float* out = (float*)d_out;
    yolo_fused_kernel<<<TOTAL_BLOCKS, DENSE_THREADS>>>(pred, target, tsz, out);
}

// round 12
// speedup vs baseline: 1.3740x; 1.0550x over previous
#include <cuda_runtime.h>
#include <math.h>

#define NB_ 16
#define NA_ 5
#define NH_ 96
#define NW_ 96
#define MAXT_ 50
#define NCLS_ 40
#define TROW_ 53
#define CH_ 45
#define NTOT_ (NB_*NA_*NH_*NW_)      // 737280
#define DENSE_BLOCKS 360
#define DENSE_THREADS 256
#define EPT 8                         // 360*256*8 = 737280 exactly
#define TOTAL_BLOCKS (NB_ + DENSE_BLOCKS)   // 376 blocks, one wave

__constant__ float c_aw[NA_] = {1.f, 2.f, 4.f, 2.f, 4.f};
__constant__ float c_ah[NA_] = {1.f, 2.f, 4.f, 4.f, 2.f};

struct Acc {
    double S;          // sum softplus(pred_conf) over ALL cells
    double corr_conf;  // corrections at modified cells for cmf*bce
    double mask_bce;   // sum over mask cells of bce(p, tconf=1)
    double lx, ly, lw, lh, lcls;
    int nM;
    int cmf_removed;   // modified cells with cmf==0
    int nGT;
    int nCorrect;
    int nProp;
};
__device__ Acc g_acc;                 // zero-initialized at module load
__device__ unsigned int g_done;       // zero-initialized

// Fast softplus: 2 MUFU + few FMA. Arg of __logf is in (1,2] -> well
// conditioned; |err| ~1e-6, far inside the 1e-3 budget. Used consistently in
// both the dense sum and the sparse corrections so residuals cancel.
__device__ __forceinline__ float softplus_f(float p) {
    return fmaxf(p, 0.f) + __logf(1.f + __expf(-fabsf(p)));
}

__global__ void __launch_bounds__(DENSE_THREADS)
yolo_fused_kernel(const float* __restrict__ pred,
                  const float* __restrict__ target,
                  const int* __restrict__ tsz,
                  float* __restrict__ out) {
    const int bid = blockIdx.x;
    const int tid = threadIdx.x;

    if (bid >= NB_) {
        // ===================== DENSE path: conf-channel reduction =====================
        const int gt = (bid - NB_) * DENSE_THREADS + tid;
        // Issue ALL loads first. Streaming (.cs): single-use data, evict-first,
        // and the candidate lever for sector-granularity DRAM fetch.
        float v[EPT];
        #pragma unroll
        for (int k = 0; k < EPT; k++) {
            int i = gt + k * (DENSE_BLOCKS * DENSE_THREADS);
            v[k] = __ldcs(pred + i * CH_);   // i*45 < 2^25, fits int
        }
        float sp = 0.f;
        int np = 0;
        #pragma unroll
        for (int k = 0; k < EPT; k++) {
            sp += softplus_f(v[k]);
            np += (v[k] > 0.f) ? 1 : 0;
        }
        #pragma unroll
        for (int off = 16; off > 0; off >>= 1) {
            sp += __shfl_down_sync(0xffffffffu, sp, off);
            np += __shfl_down_sync(0xffffffffu, np, off);
        }
        __shared__ float ssp[8];
        __shared__ int snp[8];
        int wid = tid >> 5, lid = tid & 31;
        if (lid == 0) { ssp[wid] = sp; snp[wid] = np; }
        __syncthreads();
        if (wid == 0) {
            sp = (lid < 8) ? ssp[lid] : 0.f;
            np = (lid < 8) ? snp[lid] : 0;
            #pragma unroll
            for (int off = 4; off > 0; off >>= 1) {
                sp += __shfl_down_sync(0xffffffffu, sp, off);
                np += __shfl_down_sync(0xffffffffu, np, off);
            }
            if (lid == 0) {
                atomicAdd(&g_acc.S, (double)sp);
                atomicAdd(&g_acc.nProp, np);
            }
        }
    } else {
        // ===================== BUILD path (one block per batch, bid 0..15) =====
        const int b = bid;
        __shared__ float s_gx[MAXT_], s_gy[MAXT_], s_gw[MAXT_], s_gh[MAXT_];
        __shared__ float s_tx[MAXT_], s_ty[MAXT_], s_tw[MAXT_], s_th[MAXT_];
        __shared__ int   s_cell[MAXT_];            // cj*NW + ci
        __shared__ int   s_best[MAXT_], s_lbl[MAXT_], s_ign[MAXT_];  // ign = 5-bit mask
        __shared__ int   s_rlist[MAXT_];
        __shared__ int   s_ne;

        const int size = tsz[b];
        if (tid == 0) s_ne = 0;

        // ---- Phase A: per-target independent quantities (parallel) ----
        if (tid < size) {
            const float* row = target + ((size_t)b * MAXT_ + tid) * TROW_;
            const float inv = 1.f / 16.f;
            float gx = row[0] * inv;
            float gy = row[1] * inv;
            float gh = row[3] * inv;   // row[3] = h
            float gw = row[4] * inv;   // row[4] = w
            int gi = (int)gx;
            int gj = (int)gy;
            float bestv = -1e30f; int bestn = 0;
            int ignm = 0;
            float ga = (gw + 1.f) * (gh + 1.f);
            #pragma unroll
            for (int a = 0; a < NA_; a++) {
                float iw = fmaxf(fminf(gw, c_aw[a]) + 1.f, 0.f);
                float ih = fmaxf(fminf(gh, c_ah[a]) + 1.f, 0.f);
                float inter = iw * ih;
                float aa = (c_aw[a] + 1.f) * (c_ah[a] + 1.f);
                float iou = inter / (ga + aa - inter + 1e-16f);
                if (iou > 0.5f) ignm |= (1 << a);
                if (iou > bestv) { bestv = iou; bestn = a; }
            }
            const float* cl = row + 13;
            float bv = cl[0]; int ba = 0;
            #pragma unroll
            for (int k = 1; k < NCLS_; k++) {
                float v = cl[k];
                if (v > bv) { bv = v; ba = k; }
            }
            s_gx[tid] = gx; s_gy[tid] = gy; s_gw[tid] = gw; s_gh[tid] = gh;
            s_tx[tid] = gx - (float)gi;
            s_ty[tid] = gy - (float)gj;
            s_tw[tid] = logf(gw / c_aw[bestn] + 1e-16f);
            s_th[tid] = logf(gh / c_ah[bestn] + 1e-16f);
            s_cell[tid] = gj * NW_ + gi;
            s_best[tid] = bestn; s_lbl[tid] = ba; s_ign[tid] = ignm;
        }
        __syncthreads();

        // ---- Phase B: cell-representative detection + nCorrect (parallel) ----
        if (tid < size) {
            int cell = s_cell[tid];
            bool rep = true;
            for (int t = 0; t < tid; t++)
                if (s_cell[t] == cell) { rep = false; break; }
            if (rep) {
                int pos = atomicAdd(&s_ne, 1);
                s_rlist[pos] = tid;
            }

            // nCorrect: scan-order independent (per target)
            int bn = s_best[tid];
            int ci = cell % NW_, cj = cell / NW_;
            const float* c = pred + ((((size_t)b * NA_ + bn) * NH_ + cj) * NW_ + ci) * CH_;
            float pc = c[0], x = c[1], y = c[2], h = c[3], w = c[4];
            float bv = c[5]; int ba = 0;
            #pragma unroll
            for (int k = 1; k < NCLS_; k++) {
                float v = c[5 + k];
                if (v > bv) { bv = v; ba = k; }
            }
            float px = x + (float)ci;
            float py = y + (float)cj;
            float pw = expf(w) * c_aw[bn];
            float ph = expf(h) * c_ah[bn];
            float gx = s_gx[tid], gy = s_gy[tid], gw = s_gw[tid], gh = s_gh[tid];
            float gx1 = gx - gw * 0.5f, gx2 = gx + gw * 0.5f;
            float gy1 = gy - gh * 0.5f, gy2 = gy + gh * 0.5f;
            float px1 = px - pw * 0.5f, px2 = px + pw * 0.5f;
            float py1 = py - ph * 0.5f, py2 = py + ph * 0.5f;
            float iw = fmaxf(fminf(gx2, px2) - fmaxf(gx1, px1) + 1.f, 0.f);
            float ih = fmaxf(fminf(gy2, py2) - fmaxf(gy1, py1) + 1.f, 0.f);
            float inter = iw * ih;
            float gaA = (gx2 - gx1 + 1.f) * (gy2 - gy1 + 1.f);
            float paA = (px2 - px1 + 1.f) * (py2 - py1 + 1.f);
            float iou = inter / (gaA + paA - inter + 1e-16f);
            if (iou > 0.5f && ba == s_lbl[tid] && pc > 0.5f)
                atomicAdd(&g_acc.nCorrect, 1);
        }
        if (tid == 0 && size > 0) atomicAdd(&g_acc.nGT, size);
        __syncthreads();

        // ---- Phase C: per-(cell,anchor) replay restricted to that cell (parallel) ----
        const int ne = s_ne;
        for (int idx = tid; idx < ne * NA_; idx += blockDim.x) {
            int e = idx / NA_, a = idx % NA_;
            int cell = s_cell[s_rlist[e]];
            int cm = 1, m = 0, src = -1;
            for (int t = 0; t < size; t++) {
                if (s_cell[t] == cell) {
                    if ((s_ign[t] >> a) & 1) cm = 0;
                    if (s_best[t] == a) { cm = 1; m = 1; src = t; }
                }
            }
            int ci = cell % NW_, cj = cell / NW_;
            const float* c = pred + ((((size_t)b * NA_ + a) * NH_ + cj) * NW_ + ci) * CH_;
            float p = c[0];
            int cmf = (cm != m);
            if (cmf) {
                if (m) atomicAdd(&g_acc.corr_conf, (double)(-p));
                // cm=1,m=0: bce == softplus(p) already counted by dense S; correction 0
            } else {
                atomicAdd(&g_acc.corr_conf, (double)(-softplus_f(p)));
                atomicAdd(&g_acc.cmf_removed, 1);
            }
            if (m) {
                atomicAdd(&g_acc.nM, 1);
                float bce1 = softplus_f(p) - p;   // bce with tconf=1
                atomicAdd(&g_acc.mask_bce, (double)bce1);
                float x = c[1], y = c[2], h = c[3], w = c[4];
                float dx = x - s_tx[src];
                float dy = y - s_ty[src];
                float dw = w - s_tw[src];
                float dh = h - s_th[src];
                atomicAdd(&g_acc.lx, (double)(dx * dx));
                atomicAdd(&g_acc.ly, (double)(dy * dy));
                atomicAdd(&g_acc.lw, (double)(dw * dw));
                atomicAdd(&g_acc.lh, (double)(dh * dh));
                float mx = c[5];
                #pragma unroll
                for (int k = 1; k < NCLS_; k++) mx = fmaxf(mx, c[5 + k]);
                float s = 0.f;
                #pragma unroll
                for (int k = 0; k < NCLS_; k++) s += expf(c[5 + k] - mx);
                float ce = mx + logf(s) - c[5 + s_lbl[src]];
                atomicAdd(&g_acc.lcls, (double)ce);
            }
        }
    }

    // ===================== Last block finalizes + resets state =====================
    __syncthreads();
    if (tid == 0) {
        __threadfence();
        unsigned int old = atomicAdd(&g_done, 1u);
        if (old == gridDim.x - 1) {
            __threadfence();
            Acc a = g_acc;
            double sum_cmf = (double)NTOT_ - (double)a.cmf_removed;
            double nM = (double)a.nM;
            double conf = (a.S + a.corr_conf) / sum_cmf + a.mask_bce / nM;
            double coord = (a.lx + a.ly + a.lw + a.lh) / nM;
            double cls = a.lcls / (nM * (double)NB_);
            out[0] = (float)(coord + conf + cls);
            out[1] = (float)coord;
            out[2] = (float)conf;
            out[3] = (float)cls;
            float nGT = fmaxf((float)a.nGT, 1.f);
            out[4] = (float)a.nCorrect / nGT;
            out[5] = (a.nProp > 0) ? ((float)a.nCorrect / fmaxf((float)a.nProp, 1.f)) : 1.f;
            // Reset accumulators for the next graph replay (deterministic:
            // module-load zero-init covers the very first call).
            g_acc.S = 0.0; g_acc.corr_conf = 0.0; g_acc.mask_bce = 0.0;
            g_acc.lx = 0.0; g_acc.ly = 0.0; g_acc.lw = 0.0; g_acc.lh = 0.0;
            g_acc.lcls = 0.0;
            g_acc.nM = 0; g_acc.cmf_removed = 0; g_acc.nGT = 0;
            g_acc.nCorrect = 0; g_acc.nProp = 0;
            __threadfence();
            g_done = 0u;
        }
    }
}

extern "C" void kernel_launch(void* const* d_in, const int* in_sizes, int n_in,
                              void* d_out, int out_size) {
    const float* pred = (const float*)d_in[0];
    const float* target = (const float*)d_in[1];
    const int* tsz = (const int*)d_in[2];
    float* out = (float*)d_out;
    yolo_fused_kernel<<<TOTAL_BLOCKS, DENSE_THREADS>>>(pred, target, tsz, out);
}